// round 1
// baseline (speedup 1.0000x reference)
#include <cuda_runtime.h>
#include <cuda_bf16.h>
#include <math.h>

// Problem constants
#define BB 64
#define TT 64
#define LL 400
#define EE 256
#define HH 512
#define H2 1024      // 2H
#define H4 2048      // 4H
#define KCAT 768     // E + H (gate GEMM K)
#define BH (BB*HH)   // 32768

// d_out layout: outputs[T,B,H] | h[B,H] | c[B,H] | attn[T,B,L] | p_gens[T,B,1]
#define OUT_OUTPUTS 0
#define OUT_H  2097152
#define OUT_C  2129920
#define OUT_ATTN 2162688
#define OUT_PG 3801088

// ---------------- scratch (static device arrays; no allocation) ----------------
__device__ float g_enc_feat[BB*LL*HH];       // 52.4 MB
__device__ float g_Wcat[H4*KCAT];            // interleaved [4j+g][E+H]
__device__ float g_bcomb[H4];
__device__ float g_u[EE];
__device__ float g_sx[TT*BB];
__device__ float g_hbuf[2*BH];
__device__ float g_cbuf[2*BH];
__device__ float g_dec[BB*HH];
__device__ float g_ctx[BB*H2];

__device__ __forceinline__ float sigmoidf_(float x) { return 1.f/(1.f+__expf(-x)); }

// ---------------------------------------------------------------------------
// P1: build interleaved combined gate weights.
// x = inp @ A^T (A = in2x_w[:, :E]); gates = x@W_ih^T + h@W_hh^T + biases
//   => gates = inp @ (W_ih A)^T + h @ W_hh^T + bcomb
// Row permutation: stored row rp = 4*j + g  <->  original row g*H + j
// so a thread owning 4 consecutive output columns holds one LSTM unit's (i,f,g,o).
// ---------------------------------------------------------------------------
__global__ __launch_bounds__(256) void k_wcat(
    const float* __restrict__ W_ih, const float* __restrict__ in2x_w,
    const float* __restrict__ in2x_b, const float* __restrict__ b_ih,
    const float* __restrict__ b_hh, const float* __restrict__ W_hh,
    float* __restrict__ Wcat, float* __restrict__ bcomb)
{
    int rp = blockIdx.x;            // 0..2047
    int g = rp & 3, j = rp >> 2;
    int orow = g*HH + j;
    int tid = threadIdx.x;
    __shared__ float wrow[EE];
    __shared__ float red[256];
    wrow[tid] = W_ih[orow*EE + tid];
    __syncthreads();
    // columns 0..255: (W_ih @ A)[rp][c]
    float s = 0.f;
    #pragma unroll 8
    for (int i = 0; i < EE; i++) s += wrow[i] * in2x_w[i*1280 + tid];
    Wcat[rp*KCAT + tid] = s;
    // columns 256..767: W_hh row
    Wcat[rp*KCAT + 256 + tid] = W_hh[orow*HH + tid];
    Wcat[rp*KCAT + 512 + tid] = W_hh[orow*HH + 256 + tid];
    // bias: W_ih row . in2x_b + b_ih + b_hh
    red[tid] = wrow[tid] * in2x_b[tid];
    __syncthreads();
    for (int st = 128; st > 0; st >>= 1) {
        if (tid < st) red[tid] += red[tid+st];
        __syncthreads();
    }
    if (tid == 0) bcomb[rp] = red[0] + b_ih[orow] + b_hh[orow];
}

// P2a: u[j] = sum_i Wpg_w[2048+i] * in2x_w[i*1280 + j]   (x-portion of p_gen folded)
__global__ __launch_bounds__(256) void k_u(
    const float* __restrict__ Wpg, const float* __restrict__ in2x_w,
    float* __restrict__ u)
{
    int j = threadIdx.x;
    float s = 0.f;
    #pragma unroll 8
    for (int i = 0; i < EE; i++) s += Wpg[2048 + i] * in2x_w[i*1280 + j];
    u[j] = s;
}

// P2b: sx[t,b] = inp[t,b,:].u + Wpg_b
__global__ __launch_bounds__(256) void k_sx(
    const float* __restrict__ inp, const float* __restrict__ u,
    const float* __restrict__ Wpg_b, float* __restrict__ sx)
{
    int w = blockIdx.x*8 + (threadIdx.x >> 5);
    int lane = threadIdx.x & 31;
    const float* row = inp + (size_t)w*EE;
    float s = 0.f;
    #pragma unroll
    for (int q = 0; q < 8; q++) s += row[lane + 32*q] * u[lane + 32*q];
    #pragma unroll
    for (int o = 16; o > 0; o >>= 1) s += __shfl_xor_sync(0xffffffffu, s, o);
    if (lane == 0) sx[w] = s + Wpg_b[0];
}

// ---------------------------------------------------------------------------
// P3: enc_feat = encoder_states @ Wh_w^T + Wh_b.  M=25600, N=512, K=1024, fp32.
// BM=BN=64, BK=32, 256 threads, 4x4 per thread.
// ---------------------------------------------------------------------------
__global__ __launch_bounds__(256) void k_encfeat(
    const float* __restrict__ A, const float* __restrict__ W,
    const float* __restrict__ bias, float* __restrict__ C)
{
    __shared__ float As[32][68];
    __shared__ float Ws[32][68];
    int tid = threadIdx.x;
    int m = tid >> 2, kq = tid & 3;
    int tr = tid >> 4, tc = tid & 15;
    float acc[4][4];
    #pragma unroll
    for (int i = 0; i < 4; i++)
        #pragma unroll
        for (int jj = 0; jj < 4; jj++) acc[i][jj] = 0.f;

    const float* Ap = A + ((size_t)(blockIdx.y*64 + m))*H2;
    const float* Wp = W + ((size_t)(blockIdx.x*64 + m))*H2;

    for (int k0 = 0; k0 < H2; k0 += 32) {
        #pragma unroll
        for (int q = 0; q < 2; q++) {
            int kk0 = q*16 + kq*4;
            float4 a4 = *(const float4*)(Ap + k0 + kk0);
            float4 w4 = *(const float4*)(Wp + k0 + kk0);
            As[kk0+0][m] = a4.x; As[kk0+1][m] = a4.y; As[kk0+2][m] = a4.z; As[kk0+3][m] = a4.w;
            Ws[kk0+0][m] = w4.x; Ws[kk0+1][m] = w4.y; Ws[kk0+2][m] = w4.z; Ws[kk0+3][m] = w4.w;
        }
        __syncthreads();
        #pragma unroll
        for (int k = 0; k < 32; k++) {
            float4 av = *(const float4*)&As[k][tr*4];
            float4 wv = *(const float4*)&Ws[k][tc*4];
            float a_[4] = {av.x, av.y, av.z, av.w};
            float w_[4] = {wv.x, wv.y, wv.z, wv.w};
            #pragma unroll
            for (int i = 0; i < 4; i++)
                #pragma unroll
                for (int jj = 0; jj < 4; jj++)
                    acc[i][jj] += a_[i]*w_[jj];
        }
        __syncthreads();
    }
    int colb = blockIdx.x*64 + tc*4;
    float4 b4 = *(const float4*)(bias + colb);
    #pragma unroll
    for (int i = 0; i < 4; i++) {
        size_t row = (size_t)(blockIdx.y*64 + tr*4 + i);
        float4 o;
        o.x = acc[i][0] + b4.x; o.y = acc[i][1] + b4.y;
        o.z = acc[i][2] + b4.z; o.w = acc[i][3] + b4.w;
        *(float4*)(C + row*HH + colb) = o;
    }
}

// ---------------------------------------------------------------------------
// S1: gates = [inp_t | h] @ Wcat^T + bcomb  -> fused LSTM elementwise.
// M=64(all batch), N-tile=16 (4 quads), K=768, grid 128 blocks.
// ---------------------------------------------------------------------------
__global__ __launch_bounds__(256) void k_gates_lstm(
    const float* __restrict__ inp, const float* __restrict__ hsrc,
    const float* __restrict__ csrc, float* __restrict__ hdst,
    float* __restrict__ cdst, const float* __restrict__ Wcat,
    const float* __restrict__ bcomb)
{
    __shared__ float As[64*33];
    __shared__ float Ws[16*33];
    int tid = threadIdx.x;
    int b = tid & 63, qb = tid >> 6;
    float acc0=0.f, acc1=0.f, acc2=0.f, acc3=0.f;
    int nbase = blockIdx.x * 16;

    for (int k0 = 0; k0 < KCAT; k0 += 32) {
        #pragma unroll
        for (int q = 0; q < 8; q++) {
            int lin = tid + q*256;
            int k = lin & 31, m = lin >> 5;
            int kg = k0 + k;
            As[m*33 + k] = (kg < EE) ? inp[m*EE + kg] : hsrc[m*HH + (kg - EE)];
        }
        #pragma unroll
        for (int q = 0; q < 2; q++) {
            int lin = tid + q*256;
            int k = lin & 31, n = lin >> 5;
            Ws[n*33 + k] = Wcat[(size_t)(nbase + n)*KCAT + k0 + k];
        }
        __syncthreads();
        #pragma unroll
        for (int kk = 0; kk < 32; kk++) {
            float a = As[b*33 + kk];
            acc0 += a * Ws[(qb*4+0)*33 + kk];
            acc1 += a * Ws[(qb*4+1)*33 + kk];
            acc2 += a * Ws[(qb*4+2)*33 + kk];
            acc3 += a * Ws[(qb*4+3)*33 + kk];
        }
        __syncthreads();
    }
    int j = blockIdx.x*4 + qb;   // LSTM unit index
    float iv = sigmoidf_(acc0 + bcomb[j*4+0]);
    float fv = sigmoidf_(acc1 + bcomb[j*4+1]);
    float gv = tanhf    (acc2 + bcomb[j*4+2]);
    float ov = sigmoidf_(acc3 + bcomb[j*4+3]);
    float cn = fv * csrc[b*HH + j] + iv * gv;
    float hn = ov * tanhf(cn);
    cdst[b*HH + j] = cn;
    hdst[b*HH + j] = hn;
}

// ---------------------------------------------------------------------------
// Generic small GEMM: out[b,n] = [src0|src1][b,:] . W[n,:] + bias[n]
// M=64, N-tile=8, grid N/8 blocks, 256 threads, 2 outputs/thread.
// ---------------------------------------------------------------------------
__global__ __launch_bounds__(256) void k_gemm64(
    const float* __restrict__ src0, int w0, const float* __restrict__ src1,
    int K, const float* __restrict__ W, const float* __restrict__ bias,
    float* __restrict__ out, int N)
{
    __shared__ float As[64*33];
    __shared__ float Ws[8*33];
    int tid = threadIdx.x;
    int b = tid & 63, nl = tid >> 6;
    int w1 = K - w0;
    float acc0 = 0.f, acc1 = 0.f;

    for (int k0 = 0; k0 < K; k0 += 32) {
        #pragma unroll
        for (int q = 0; q < 8; q++) {
            int lin = tid + q*256;
            int k = lin & 31, m = lin >> 5;
            int kg = k0 + k;
            As[m*33 + k] = (kg < w0) ? src0[m*w0 + kg] : src1[m*w1 + (kg - w0)];
        }
        {
            int k = tid & 31, n = tid >> 5;
            Ws[n*33 + k] = W[(size_t)(blockIdx.x*8 + n)*K + k0 + k];
        }
        __syncthreads();
        #pragma unroll
        for (int kk = 0; kk < 32; kk++) {
            float a = As[b*33 + kk];
            acc0 += a * Ws[nl*33 + kk];
            acc1 += a * Ws[(nl+4)*33 + kk];
        }
        __syncthreads();
    }
    int n0 = blockIdx.x*8 + nl, n1 = n0 + 4;
    out[b*N + n0] = acc0 + bias[n0];
    out[b*N + n1] = acc1 + bias[n1];
}

// ---------------------------------------------------------------------------
// S3: fused attention per batch row b (grid=64, 256 threads):
//   e[l] = sum_h v[h]*tanh(enc_feat[b,l,h] + dec[b,h])
//   masked renormalized softmax -> a  (written to d_out attn region)
//   ctx[b,:] = sum_l a[l]*enc_states[b,l,:]
//   p_gen[b] = sigmoid(ctx.wpg + h.wpg' + c.wpg'' + sx[t,b])
// ---------------------------------------------------------------------------
__global__ __launch_bounds__(256) void k_attention(
    const float* __restrict__ enc_feat, const float* __restrict__ dec,
    const float* __restrict__ v, const float* __restrict__ mask,
    const float* __restrict__ enc_states, const float* __restrict__ Wpg,
    const float* __restrict__ h, const float* __restrict__ c,
    const float* __restrict__ sx_t, float* __restrict__ ctx_out,
    float* __restrict__ attn_out, float* __restrict__ pg_out)
{
    int b = blockIdx.x, tid = threadIdx.x;
    __shared__ __align__(16) float s_dec[HH];
    __shared__ __align__(16) float s_v[HH];
    __shared__ float s_e[LL];
    __shared__ float s_red[8];
    s_dec[tid]       = dec[b*HH + tid];
    s_dec[tid + 256] = dec[b*HH + tid + 256];
    s_v[tid]         = v[tid];
    s_v[tid + 256]   = v[tid + 256];
    __syncthreads();

    int warp = tid >> 5, lane = tid & 31;
    const float4* dv = (const float4*)s_dec;
    const float4* vv = (const float4*)s_v;

    // Phase A: scores
    for (int it = 0; it < 50; it++) {
        int l = warp + it*8;
        const float4* row = (const float4*)(enc_feat + ((size_t)(b*LL + l))*HH);
        float s = 0.f;
        #pragma unroll
        for (int q = 0; q < 4; q++) {
            float4 f = row[lane + 32*q];
            float4 d = dv [lane + 32*q];
            float4 w = vv [lane + 32*q];
            s += w.x*tanhf(f.x + d.x) + w.y*tanhf(f.y + d.y)
               + w.z*tanhf(f.z + d.z) + w.w*tanhf(f.w + d.w);
        }
        #pragma unroll
        for (int o = 16; o > 0; o >>= 1) s += __shfl_xor_sync(0xffffffffu, s, o);
        if (lane == 0) s_e[l] = s;
    }
    __syncthreads();

    // Phase B: masked renormalized softmax
    float m = -1e30f;
    for (int l = tid; l < LL; l += 256) m = fmaxf(m, s_e[l]);
    #pragma unroll
    for (int o = 16; o > 0; o >>= 1) m = fmaxf(m, __shfl_xor_sync(0xffffffffu, m, o));
    if (lane == 0) s_red[warp] = m;
    __syncthreads();
    m = s_red[0];
    #pragma unroll
    for (int w = 1; w < 8; w++) m = fmaxf(m, s_red[w]);

    float ssum = 0.f;
    for (int l = tid; l < LL; l += 256) {
        float ex = __expf(s_e[l] - m) * mask[b*LL + l];
        s_e[l] = ex;
        ssum += ex;
    }
    #pragma unroll
    for (int o = 16; o > 0; o >>= 1) ssum += __shfl_xor_sync(0xffffffffu, ssum, o);
    __syncthreads();
    if (lane == 0) s_red[warp] = ssum;
    __syncthreads();
    ssum = 0.f;
    #pragma unroll
    for (int w = 0; w < 8; w++) ssum += s_red[w];
    float inv = 1.f / ssum;
    for (int l = tid; l < LL; l += 256) {
        float a = s_e[l] * inv;
        s_e[l] = a;
        attn_out[b*LL + l] = a;
    }
    __syncthreads();

    // Phase C: ctx (each thread: 4 consecutive channels)
    float4 acc = make_float4(0.f, 0.f, 0.f, 0.f);
    const float4* es = (const float4*)(enc_states + (size_t)b*LL*H2);
    #pragma unroll 4
    for (int l = 0; l < LL; l++) {
        float al = s_e[l];
        float4 f = es[l*256 + tid];
        acc.x += al*f.x; acc.y += al*f.y; acc.z += al*f.z; acc.w += al*f.w;
    }
    ((float4*)(ctx_out + b*H2))[tid] = acc;

    // Phase D: p_gen
    float4 w4 = ((const float4*)Wpg)[tid];                 // ctx portion 0..1023
    float p = acc.x*w4.x + acc.y*w4.y + acc.z*w4.z + acc.w*w4.w;
    int d0 = 2*tid;
    p += h[b*HH + d0]   * Wpg[1024 + d0]   + h[b*HH + d0+1] * Wpg[1024 + d0+1];
    p += c[b*HH + d0]   * Wpg[1536 + d0]   + c[b*HH + d0+1] * Wpg[1536 + d0+1];
    #pragma unroll
    for (int o = 16; o > 0; o >>= 1) p += __shfl_xor_sync(0xffffffffu, p, o);
    __syncthreads();
    if (lane == 0) s_red[warp] = p;
    __syncthreads();
    if (tid == 0) {
        float tot = 0.f;
        #pragma unroll
        for (int w = 0; w < 8; w++) tot += s_red[w];
        pg_out[b] = 1.f/(1.f + __expf(-(tot + sx_t[b])));
    }
}

__global__ __launch_bounds__(256) void k_copy_hc(
    const float* __restrict__ h, const float* __restrict__ c, float* __restrict__ out)
{
    int i = blockIdx.x*256 + threadIdx.x;   // grid 128 -> 32768
    out[OUT_H + i] = h[i];
    out[OUT_C + i] = c[i];
}

// ---------------------------------------------------------------------------
extern "C" void kernel_launch(void* const* d_in, const int* in_sizes, int n_in,
                              void* d_out, int out_size)
{
    const float* dec_in     = (const float*)d_in[0];
    const float* init_h     = (const float*)d_in[1];
    const float* init_c     = (const float*)d_in[2];
    const float* enc_states = (const float*)d_in[3];
    const float* maskp      = (const float*)d_in[4];
    const float* Ws_w       = (const float*)d_in[5];
    const float* Ws_b       = (const float*)d_in[6];
    const float* in2x_w     = (const float*)d_in[7];
    const float* in2x_b     = (const float*)d_in[8];
    const float* Wpg_w      = (const float*)d_in[9];
    const float* Wpg_b      = (const float*)d_in[10];
    const float* Wout_w     = (const float*)d_in[11];
    const float* Wout_b     = (const float*)d_in[12];
    const float* Wh_w       = (const float*)d_in[13];
    const float* Wh_b       = (const float*)d_in[14];
    const float* vptr       = (const float*)d_in[15];
    const float* W_ih       = (const float*)d_in[16];
    const float* W_hh       = (const float*)d_in[17];
    const float* b_ih       = (const float*)d_in[18];
    const float* b_hh       = (const float*)d_in[19];
    float* out = (float*)d_out;

    float *p_ef, *p_wcat, *p_bc, *p_u, *p_sx, *p_h, *p_c, *p_dec, *p_ctx;
    cudaGetSymbolAddress((void**)&p_ef,   g_enc_feat);
    cudaGetSymbolAddress((void**)&p_wcat, g_Wcat);
    cudaGetSymbolAddress((void**)&p_bc,   g_bcomb);
    cudaGetSymbolAddress((void**)&p_u,    g_u);
    cudaGetSymbolAddress((void**)&p_sx,   g_sx);
    cudaGetSymbolAddress((void**)&p_h,    g_hbuf);
    cudaGetSymbolAddress((void**)&p_c,    g_cbuf);
    cudaGetSymbolAddress((void**)&p_dec,  g_dec);
    cudaGetSymbolAddress((void**)&p_ctx,  g_ctx);

    // Precompute
    k_wcat<<<H4, 256>>>(W_ih, in2x_w, in2x_b, b_ih, b_hh, W_hh, p_wcat, p_bc);
    k_u<<<1, 256>>>(Wpg_w, in2x_w, p_u);
    k_sx<<<512, 256>>>(dec_in, p_u, Wpg_b, p_sx);
    k_encfeat<<<dim3(8, 400), 256>>>(enc_states, Wh_w, Wh_b, p_ef);

    // Sequential decode
    for (int t = 0; t < TT; t++) {
        const float* hsrc = (t == 0) ? init_h : p_h + ((t + 1) & 1)*BH;
        const float* csrc = (t == 0) ? init_c : p_c + ((t + 1) & 1)*BH;
        float* hdst = p_h + (t & 1)*BH;
        float* cdst = p_c + (t & 1)*BH;

        k_gates_lstm<<<128, 256>>>(dec_in + (size_t)t*BB*EE, hsrc, csrc,
                                   hdst, cdst, p_wcat, p_bc);
        k_gemm64<<<64, 256>>>(hdst, HH, cdst, H2, Ws_w, Ws_b, p_dec, HH);
        k_attention<<<64, 256>>>(p_ef, p_dec, vptr, maskp, enc_states, Wpg_w,
                                 hdst, cdst, p_sx + t*BB, p_ctx,
                                 out + OUT_ATTN + (size_t)t*BB*LL,
                                 out + OUT_PG + t*BB);
        k_gemm64<<<64, 256>>>(hdst, HH, p_ctx, HH + H2, Wout_w, Wout_b,
                              out + OUT_OUTPUTS + (size_t)t*BB*HH, HH);
    }
    k_copy_hc<<<128, 256>>>(p_h + BH, p_c + BH, out);
}

// round 2
// speedup vs baseline: 3.7412x; 3.7412x over previous
#include <cuda_runtime.h>
#include <cuda_bf16.h>
#include <math.h>

// Problem constants
#define BB 64
#define TT 64
#define LL 400
#define EE 256
#define HH 512
#define H2 1024      // 2H
#define H4 2048      // 4H
#define KCAT 768     // E + H (gate GEMM K)
#define BH (BB*HH)   // 32768

// d_out layout: outputs[T,B,H] | h[B,H] | c[B,H] | attn[T,B,L] | p_gens[T,B,1]
#define OUT_OUTPUTS 0
#define OUT_H  2097152
#define OUT_C  2129920
#define OUT_ATTN 2162688
#define OUT_PG 3801088

// ---------------- scratch (static device arrays; no allocation) ----------------
__device__ float g_enc_feat[BB*LL*HH];       // 52.4 MB
__device__ float g_Wcat[H4*KCAT];            // interleaved [4j+g][E+H]
__device__ float g_bcomb[H4];
__device__ float g_u[EE];
__device__ float g_sx[TT*BB];
__device__ float g_hbuf[2*BH];
__device__ float g_cbuf[2*BH];
__device__ float g_ctx[BB*H2];
__device__ float g_e[BB*LL];
__device__ float g_gpart[6*BB*H4];           // gates split-K partials
__device__ float g_dpart[8*BB*HH];           // dec split-K partials
__device__ float g_opart[12*BB*HH];          // out split-K partials
__device__ float g_cpart[16*BB*H2];          // ctx l-split partials (4 MB)

__device__ __forceinline__ float sigmoidf_(float x) { return 1.f/(1.f+__expf(-x)); }

// ---------------------------------------------------------------------------
// P1: build interleaved combined gate weights.
// gates = inp @ (W_ih A)^T + h @ W_hh^T + bcomb ; row perm rp = 4*j + g.
// ---------------------------------------------------------------------------
__global__ __launch_bounds__(256) void k_wcat(
    const float* __restrict__ W_ih, const float* __restrict__ in2x_w,
    const float* __restrict__ in2x_b, const float* __restrict__ b_ih,
    const float* __restrict__ b_hh, const float* __restrict__ W_hh,
    float* __restrict__ Wcat, float* __restrict__ bcomb)
{
    int rp = blockIdx.x;            // 0..2047
    int g = rp & 3, j = rp >> 2;
    int orow = g*HH + j;
    int tid = threadIdx.x;
    __shared__ float wrow[EE];
    __shared__ float red[256];
    wrow[tid] = W_ih[orow*EE + tid];
    __syncthreads();
    float s = 0.f;
    #pragma unroll 8
    for (int i = 0; i < EE; i++) s += wrow[i] * in2x_w[i*1280 + tid];
    Wcat[rp*KCAT + tid] = s;
    Wcat[rp*KCAT + 256 + tid] = W_hh[orow*HH + tid];
    Wcat[rp*KCAT + 512 + tid] = W_hh[orow*HH + 256 + tid];
    red[tid] = wrow[tid] * in2x_b[tid];
    __syncthreads();
    for (int st = 128; st > 0; st >>= 1) {
        if (tid < st) red[tid] += red[tid+st];
        __syncthreads();
    }
    if (tid == 0) bcomb[rp] = red[0] + b_ih[orow] + b_hh[orow];
}

// P2a: u[j] = sum_i Wpg_w[2048+i] * in2x_w[i*1280 + j]
__global__ __launch_bounds__(256) void k_u(
    const float* __restrict__ Wpg, const float* __restrict__ in2x_w,
    float* __restrict__ u)
{
    int j = threadIdx.x;
    float s = 0.f;
    #pragma unroll 8
    for (int i = 0; i < EE; i++) s += Wpg[2048 + i] * in2x_w[i*1280 + j];
    u[j] = s;
}

// P2b: sx[t,b] = inp[t,b,:].u + Wpg_b
__global__ __launch_bounds__(256) void k_sx(
    const float* __restrict__ inp, const float* __restrict__ u,
    const float* __restrict__ Wpg_b, float* __restrict__ sx)
{
    int w = blockIdx.x*8 + (threadIdx.x >> 5);
    int lane = threadIdx.x & 31;
    const float* row = inp + (size_t)w*EE;
    float s = 0.f;
    #pragma unroll
    for (int q = 0; q < 8; q++) s += row[lane + 32*q] * u[lane + 32*q];
    #pragma unroll
    for (int o = 16; o > 0; o >>= 1) s += __shfl_xor_sync(0xffffffffu, s, o);
    if (lane == 0) sx[w] = s + Wpg_b[0];
}

// ---------------------------------------------------------------------------
// P3: enc_feat = encoder_states @ Wh_w^T + Wh_b.  (at fp32 SIMT wall; keep)
// ---------------------------------------------------------------------------
__global__ __launch_bounds__(256) void k_encfeat(
    const float* __restrict__ A, const float* __restrict__ W,
    const float* __restrict__ bias, float* __restrict__ C)
{
    __shared__ float As[32][68];
    __shared__ float Ws[32][68];
    int tid = threadIdx.x;
    int m = tid >> 2, kq = tid & 3;
    int tr = tid >> 4, tc = tid & 15;
    float acc[4][4];
    #pragma unroll
    for (int i = 0; i < 4; i++)
        #pragma unroll
        for (int jj = 0; jj < 4; jj++) acc[i][jj] = 0.f;

    const float* Ap = A + ((size_t)(blockIdx.y*64 + m))*H2;
    const float* Wp = W + ((size_t)(blockIdx.x*64 + m))*H2;

    for (int k0 = 0; k0 < H2; k0 += 32) {
        #pragma unroll
        for (int q = 0; q < 2; q++) {
            int kk0 = q*16 + kq*4;
            float4 a4 = *(const float4*)(Ap + k0 + kk0);
            float4 w4 = *(const float4*)(Wp + k0 + kk0);
            As[kk0+0][m] = a4.x; As[kk0+1][m] = a4.y; As[kk0+2][m] = a4.z; As[kk0+3][m] = a4.w;
            Ws[kk0+0][m] = w4.x; Ws[kk0+1][m] = w4.y; Ws[kk0+2][m] = w4.z; Ws[kk0+3][m] = w4.w;
        }
        __syncthreads();
        #pragma unroll
        for (int k = 0; k < 32; k++) {
            float4 av = *(const float4*)&As[k][tr*4];
            float4 wv = *(const float4*)&Ws[k][tc*4];
            float a_[4] = {av.x, av.y, av.z, av.w};
            float w_[4] = {wv.x, wv.y, wv.z, wv.w};
            #pragma unroll
            for (int i = 0; i < 4; i++)
                #pragma unroll
                for (int jj = 0; jj < 4; jj++)
                    acc[i][jj] += a_[i]*w_[jj];
        }
        __syncthreads();
    }
    int colb = blockIdx.x*64 + tc*4;
    float4 b4 = *(const float4*)(bias + colb);
    #pragma unroll
    for (int i = 0; i < 4; i++) {
        size_t row = (size_t)(blockIdx.y*64 + tr*4 + i);
        float4 o;
        o.x = acc[i][0] + b4.x; o.y = acc[i][1] + b4.y;
        o.z = acc[i][2] + b4.z; o.w = acc[i][3] + b4.w;
        *(float4*)(C + row*HH + colb) = o;
    }
}

// ---------------------------------------------------------------------------
// Generic split-K GEMM: Cpart[ks][m][n] = [src0|src1][m,:] . W[n,:] over
// K-chunk ks. M=64, BN=64, Kchunk=128. grid (N/64, K/128), 256 threads, 4x4.
// ---------------------------------------------------------------------------
__global__ __launch_bounds__(256) void k_gemm_sk(
    const float* __restrict__ src0, int w0,
    const float* __restrict__ src1, int w1,
    const float* __restrict__ W,
    float* __restrict__ Cpart, int N)
{
    __shared__ float As[32][68];
    __shared__ float Ws[32][68];
    int tid = threadIdx.x;
    int m = tid >> 2, kq = tid & 3;
    int tr = tid >> 4, tc = tid & 15;
    int K = w0 + w1;
    int koff = blockIdx.y * 128;
    int nbase = blockIdx.x * 64;
    float acc[4][4];
    #pragma unroll
    for (int i = 0; i < 4; i++)
        #pragma unroll
        for (int jj = 0; jj < 4; jj++) acc[i][jj] = 0.f;

    const float* Wp = W + (size_t)(nbase + m)*K;

    #pragma unroll
    for (int k0 = 0; k0 < 128; k0 += 32) {
        #pragma unroll
        for (int q = 0; q < 2; q++) {
            int kk0 = q*16 + kq*4;
            int kg = koff + k0 + kk0;
            float4 a4 = (kg < w0) ? *(const float4*)(src0 + m*w0 + kg)
                                  : *(const float4*)(src1 + m*w1 + kg - w0);
            float4 w4 = *(const float4*)(Wp + kg);
            As[kk0+0][m] = a4.x; As[kk0+1][m] = a4.y; As[kk0+2][m] = a4.z; As[kk0+3][m] = a4.w;
            Ws[kk0+0][m] = w4.x; Ws[kk0+1][m] = w4.y; Ws[kk0+2][m] = w4.z; Ws[kk0+3][m] = w4.w;
        }
        __syncthreads();
        #pragma unroll
        for (int k = 0; k < 32; k++) {
            float4 av = *(const float4*)&As[k][tr*4];
            float4 wv = *(const float4*)&Ws[k][tc*4];
            float a_[4] = {av.x, av.y, av.z, av.w};
            float w_[4] = {wv.x, wv.y, wv.z, wv.w};
            #pragma unroll
            for (int i = 0; i < 4; i++)
                #pragma unroll
                for (int jj = 0; jj < 4; jj++)
                    acc[i][jj] += a_[i]*w_[jj];
        }
        __syncthreads();
    }
    #pragma unroll
    for (int i = 0; i < 4; i++) {
        int row = tr*4 + i;
        float4 o = make_float4(acc[i][0], acc[i][1], acc[i][2], acc[i][3]);
        *(float4*)(Cpart + ((size_t)blockIdx.y*64 + row)*N + nbase + tc*4) = o;
    }
}

// ---------------------------------------------------------------------------
// S2: reduce gate partials (6) + bias -> LSTM elementwise -> h,c
// grid 128 x 256: thread -> (b, j)
// ---------------------------------------------------------------------------
__global__ __launch_bounds__(256) void k_lstm_ew(
    const float* __restrict__ gpart, const float* __restrict__ bcomb,
    const float* __restrict__ csrc, float* __restrict__ hdst,
    float* __restrict__ cdst)
{
    int idx = blockIdx.x*256 + threadIdx.x;   // 0..32767
    int b = idx >> 9, j = idx & 511;
    float4 g = ((const float4*)bcomb)[j];
    #pragma unroll
    for (int ks = 0; ks < 6; ks++) {
        float4 p = ((const float4*)(gpart + (size_t)ks*BB*H4 + b*H4))[j];
        g.x += p.x; g.y += p.y; g.z += p.z; g.w += p.w;
    }
    float iv = sigmoidf_(g.x);
    float fv = sigmoidf_(g.y);
    float gv = tanhf(g.z);
    float ov = sigmoidf_(g.w);
    float cn = fv * csrc[b*HH + j] + iv * gv;
    float hn = ov * tanhf(cn);
    cdst[b*HH + j] = cn;
    hdst[b*HH + j] = hn;
}

// ---------------------------------------------------------------------------
// S3: scores. grid (B=64, 25 chunks of 16 l), 256 thr, warp -> 2 rows.
// Fuses dec split-K reduce (8 partials + Ws_b).
// ---------------------------------------------------------------------------
__global__ __launch_bounds__(256) void k_scores(
    const float* __restrict__ ef, const float* __restrict__ dpart,
    const float* __restrict__ Ws_b, const float* __restrict__ v,
    float* __restrict__ e_out)
{
    int b = blockIdx.x, chunk = blockIdx.y;
    int tid = threadIdx.x;
    __shared__ __align__(16) float s_dec[HH];
    __shared__ __align__(16) float s_v[HH];
    #pragma unroll
    for (int i = tid; i < HH; i += 256) {
        float s = Ws_b[i];
        #pragma unroll
        for (int ks = 0; ks < 8; ks++) s += dpart[(size_t)ks*BB*HH + b*HH + i];
        s_dec[i] = s;
        s_v[i] = v[i];
    }
    __syncthreads();
    int warp = tid >> 5, lane = tid & 31;
    const float4* dv = (const float4*)s_dec;
    const float4* vv = (const float4*)s_v;
    #pragma unroll
    for (int r = 0; r < 2; r++) {
        int l = chunk*16 + warp*2 + r;
        const float4* row = (const float4*)(ef + ((size_t)(b*LL + l))*HH);
        float s = 0.f;
        #pragma unroll
        for (int q = 0; q < 4; q++) {
            float4 f = row[lane + 32*q];
            float4 d = dv [lane + 32*q];
            float4 w = vv [lane + 32*q];
            s += w.x*tanhf(f.x + d.x) + w.y*tanhf(f.y + d.y)
               + w.z*tanhf(f.z + d.z) + w.w*tanhf(f.w + d.w);
        }
        #pragma unroll
        for (int o = 16; o > 0; o >>= 1) s += __shfl_xor_sync(0xffffffffu, s, o);
        if (lane == 0) e_out[b*LL + l] = s;
    }
}

// ---------------------------------------------------------------------------
// S4: ctx partials. grid (B=64, 16 l-splits of 25), 256 thr.
// Each block recomputes the masked softmax (deterministic, cheap), writes its
// attn slice, and accumulates a partial ctx over its 25 l values.
// ---------------------------------------------------------------------------
__global__ __launch_bounds__(256) void k_ctx_part(
    const float* __restrict__ e, const float* __restrict__ mask,
    const float* __restrict__ es, float* __restrict__ attn_out,
    float* __restrict__ cpart)
{
    int b = blockIdx.x, sspl = blockIdx.y, tid = threadIdx.x;
    int warp = tid >> 5, lane = tid & 31;
    __shared__ float s_w[LL];
    __shared__ float s_red[8];

    float e0 = (tid < LL) ? e[b*LL + tid] : -1e30f;
    float e1 = (tid + 256 < LL) ? e[b*LL + tid + 256] : -1e30f;
    float lm = fmaxf(e0, e1);
    #pragma unroll
    for (int o = 16; o > 0; o >>= 1) lm = fmaxf(lm, __shfl_xor_sync(0xffffffffu, lm, o));
    if (lane == 0) s_red[warp] = lm;
    __syncthreads();
    float M = s_red[0];
    #pragma unroll
    for (int w = 1; w < 8; w++) M = fmaxf(M, s_red[w]);
    __syncthreads();

    float ex0 = 0.f, ex1 = 0.f;
    if (tid < LL)       { ex0 = __expf(e0 - M) * mask[b*LL + tid];       s_w[tid] = ex0; }
    if (tid + 256 < LL) { ex1 = __expf(e1 - M) * mask[b*LL + tid + 256]; s_w[tid + 256] = ex1; }
    float ls = ex0 + ex1;
    #pragma unroll
    for (int o = 16; o > 0; o >>= 1) ls += __shfl_xor_sync(0xffffffffu, ls, o);
    if (lane == 0) s_red[warp] = ls;
    __syncthreads();
    float S = 0.f;
    #pragma unroll
    for (int w = 0; w < 8; w++) S += s_red[w];
    float inv = 1.f / S;

    int l0 = sspl * 25;
    if (tid < 25) attn_out[b*LL + l0 + tid] = s_w[l0 + tid] * inv;

    float4 acc = make_float4(0.f, 0.f, 0.f, 0.f);
    const float4* esb = (const float4*)(es + (size_t)b*LL*H2);
    #pragma unroll 5
    for (int l = 0; l < 25; l++) {
        float a = s_w[l0 + l] * inv;
        float4 f = esb[(size_t)(l0 + l)*256 + tid];
        acc.x += a*f.x; acc.y += a*f.y; acc.z += a*f.z; acc.w += a*f.w;
    }
    ((float4*)(cpart + ((size_t)sspl*BB + b)*H2))[tid] = acc;
}

// ---------------------------------------------------------------------------
// S5: reduce ctx partials (16) -> ctx; fused p_gen.
// grid 64 x 256.
// ---------------------------------------------------------------------------
__global__ __launch_bounds__(256) void k_ctx_red_pgen(
    const float* __restrict__ cpart, const float* __restrict__ Wpg,
    const float* __restrict__ h, const float* __restrict__ c,
    const float* __restrict__ sx_t, float* __restrict__ ctx_out,
    float* __restrict__ pg_out)
{
    int b = blockIdx.x, tid = threadIdx.x;
    int warp = tid >> 5, lane = tid & 31;
    __shared__ float s_red[8];
    float4 acc = make_float4(0.f, 0.f, 0.f, 0.f);
    #pragma unroll
    for (int s = 0; s < 16; s++) {
        float4 p = ((const float4*)(cpart + ((size_t)s*BB + b)*H2))[tid];
        acc.x += p.x; acc.y += p.y; acc.z += p.z; acc.w += p.w;
    }
    ((float4*)(ctx_out + b*H2))[tid] = acc;

    float4 w4 = ((const float4*)Wpg)[tid];
    float p = acc.x*w4.x + acc.y*w4.y + acc.z*w4.z + acc.w*w4.w;
    int d0 = 2*tid;
    p += h[b*HH + d0] * Wpg[1024 + d0] + h[b*HH + d0+1] * Wpg[1024 + d0+1];
    p += c[b*HH + d0] * Wpg[1536 + d0] + c[b*HH + d0+1] * Wpg[1536 + d0+1];
    #pragma unroll
    for (int o = 16; o > 0; o >>= 1) p += __shfl_xor_sync(0xffffffffu, p, o);
    if (lane == 0) s_red[warp] = p;
    __syncthreads();
    if (tid == 0) {
        float tot = 0.f;
        #pragma unroll
        for (int w = 0; w < 8; w++) tot += s_red[w];
        pg_out[b] = 1.f/(1.f + __expf(-(tot + sx_t[b])));
    }
}

// S6: reduce out partials (12) + bias -> outputs[t]
__global__ __launch_bounds__(256) void k_out_red(
    const float* __restrict__ opart, const float* __restrict__ bias,
    float* __restrict__ outp)
{
    int i = blockIdx.x*256 + threadIdx.x;   // float4 index, 0..8191
    int b = i >> 7, n4 = i & 127;
    float4 acc = ((const float4*)bias)[n4];
    #pragma unroll
    for (int ks = 0; ks < 12; ks++) {
        float4 p = ((const float4*)(opart + (size_t)ks*BB*HH + b*HH))[n4];
        acc.x += p.x; acc.y += p.y; acc.z += p.z; acc.w += p.w;
    }
    ((float4*)(outp + b*HH))[n4] = acc;
}

__global__ __launch_bounds__(256) void k_copy_hc(
    const float* __restrict__ h, const float* __restrict__ c, float* __restrict__ out)
{
    int i = blockIdx.x*256 + threadIdx.x;   // grid 128 -> 32768
    out[OUT_H + i] = h[i];
    out[OUT_C + i] = c[i];
}

// ---------------------------------------------------------------------------
extern "C" void kernel_launch(void* const* d_in, const int* in_sizes, int n_in,
                              void* d_out, int out_size)
{
    const float* dec_in     = (const float*)d_in[0];
    const float* init_h     = (const float*)d_in[1];
    const float* init_c     = (const float*)d_in[2];
    const float* enc_states = (const float*)d_in[3];
    const float* maskp      = (const float*)d_in[4];
    const float* Ws_w       = (const float*)d_in[5];
    const float* Ws_b       = (const float*)d_in[6];
    const float* in2x_w     = (const float*)d_in[7];
    const float* in2x_b     = (const float*)d_in[8];
    const float* Wpg_w      = (const float*)d_in[9];
    const float* Wpg_b      = (const float*)d_in[10];
    const float* Wout_w     = (const float*)d_in[11];
    const float* Wout_b     = (const float*)d_in[12];
    const float* Wh_w       = (const float*)d_in[13];
    const float* Wh_b       = (const float*)d_in[14];
    const float* vptr       = (const float*)d_in[15];
    const float* W_ih       = (const float*)d_in[16];
    const float* W_hh       = (const float*)d_in[17];
    const float* b_ih       = (const float*)d_in[18];
    const float* b_hh       = (const float*)d_in[19];
    float* out = (float*)d_out;

    float *p_ef, *p_wcat, *p_bc, *p_u, *p_sx, *p_h, *p_c, *p_ctx;
    float *p_e, *p_gp, *p_dp, *p_op, *p_cp;
    cudaGetSymbolAddress((void**)&p_ef,   g_enc_feat);
    cudaGetSymbolAddress((void**)&p_wcat, g_Wcat);
    cudaGetSymbolAddress((void**)&p_bc,   g_bcomb);
    cudaGetSymbolAddress((void**)&p_u,    g_u);
    cudaGetSymbolAddress((void**)&p_sx,   g_sx);
    cudaGetSymbolAddress((void**)&p_h,    g_hbuf);
    cudaGetSymbolAddress((void**)&p_c,    g_cbuf);
    cudaGetSymbolAddress((void**)&p_ctx,  g_ctx);
    cudaGetSymbolAddress((void**)&p_e,    g_e);
    cudaGetSymbolAddress((void**)&p_gp,   g_gpart);
    cudaGetSymbolAddress((void**)&p_dp,   g_dpart);
    cudaGetSymbolAddress((void**)&p_op,   g_opart);
    cudaGetSymbolAddress((void**)&p_cp,   g_cpart);

    // Precompute
    k_wcat<<<H4, 256>>>(W_ih, in2x_w, in2x_b, b_ih, b_hh, W_hh, p_wcat, p_bc);
    k_u<<<1, 256>>>(Wpg_w, in2x_w, p_u);
    k_sx<<<512, 256>>>(dec_in, p_u, Wpg_b, p_sx);
    k_encfeat<<<dim3(8, 400), 256>>>(enc_states, Wh_w, Wh_b, p_ef);

    // Sequential decode
    for (int t = 0; t < TT; t++) {
        const float* hsrc = (t == 0) ? init_h : p_h + ((t + 1) & 1)*BH;
        const float* csrc = (t == 0) ? init_c : p_c + ((t + 1) & 1)*BH;
        float* hdst = p_h + (t & 1)*BH;
        float* cdst = p_c + (t & 1)*BH;

        // gates: [inp|h] @ Wcat^T ; N=2048, K=768 -> grid (32, 6)
        k_gemm_sk<<<dim3(32, 6), 256>>>(dec_in + (size_t)t*BB*EE, EE,
                                        hsrc, HH, p_wcat, p_gp, H4);
        k_lstm_ew<<<128, 256>>>(p_gp, p_bc, csrc, hdst, cdst);
        // dec: [h|c] @ Ws^T ; N=512, K=1024 -> grid (8, 8)
        k_gemm_sk<<<dim3(8, 8), 256>>>(hdst, HH, cdst, HH, Ws_w, p_dp, HH);
        k_scores<<<dim3(64, 25), 256>>>(p_ef, p_dp, Ws_b, vptr, p_e);
        k_ctx_part<<<dim3(64, 16), 256>>>(p_e, maskp, enc_states,
                                          out + OUT_ATTN + (size_t)t*BB*LL, p_cp);
        k_ctx_red_pgen<<<64, 256>>>(p_cp, Wpg_w, hdst, cdst, p_sx + t*BB,
                                    p_ctx, out + OUT_PG + t*BB);
        // out: [h|ctx] @ Wout^T ; N=512, K=1536 -> grid (8, 12)
        k_gemm_sk<<<dim3(8, 12), 256>>>(hdst, HH, p_ctx, H2, Wout_w, p_op, HH);
        k_out_red<<<32, 256>>>(p_op, Wout_b, out + OUT_OUTPUTS + (size_t)t*BB*HH);
    }
    k_copy_hc<<<128, 256>>>(p_h + BH, p_c + BH, out);
}

// round 4
// speedup vs baseline: 7.9414x; 2.1227x over previous
#include <cuda_runtime.h>
#include <cuda_bf16.h>
#include <math.h>

// Problem constants
#define BB 64
#define TT 64
#define LL 400
#define EE 256
#define HH 512
#define H2 1024      // 2H
#define H4 2048      // 4H
#define BH (BB*HH)   // 32768

// d_out layout: outputs[T,B,H] | h[B,H] | c[B,H] | attn[T,B,L] | p_gens[T,B,1]
#define OUT_OUTPUTS 0
#define OUT_H  2097152
#define OUT_C  2129920
#define OUT_ATTN 2162688
#define OUT_PG 3801088

// ---------------- scratch (static device arrays; no allocation) ----------------
__device__ float g_enc_feat[BB*LL*HH];       // 52.4 MB
__device__ float g_Wx[H4*EE];                // x-part weights, rp-major (2 MB)
__device__ float g_Whh[H4*HH];               // h-part weights, rp-major (4 MB)
__device__ float g_bcomb[H4];
__device__ float g_u[EE];
__device__ float g_sx[TT*BB];
__device__ float g_gx_all[TT*BB*H4];         // x-part of gates, all t (33.5 MB)
__device__ float g_gpart[4*BB*H4];           // gates split-K partials (h part)
__device__ float g_h_all[TT*BB*HH];          // all h_t  (8.4 MB)
__device__ float g_c_all[TT*BB*HH];          // all c_t
__device__ float g_dec_all[TT*BB*HH];        // dec features for all t (+Ws_b)
__device__ float g_e_all[TT*BB*LL];          // raw attention scores
__device__ float g_ctx_all[TT*BB*H2];        // all contexts (16.8 MB)

__device__ __forceinline__ float sigmoidf_(float x) { return 1.f/(1.f+__expf(-x)); }
// fast-but-accurate tanh: abs err ~1e-7 (NOT tanh.approx, which is ~6e-4)
__device__ __forceinline__ float ftanh(float x) {
    float e = __expf(2.f*x);
    return 1.f - __fdividef(2.f, e + 1.f);
}

// ---------------------------------------------------------------------------
// P1: build combined gate weights, split into Wx (K=256) and Whh (K=512).
// Row permutation rp = 4*j + g  <->  original row g*H + j.
// Wx[rp] = (W_ih @ A)[rp]  where A = in2x_w[:, :E]
// bcomb[rp] = W_ih[rp].in2x_b + b_ih + b_hh
// ---------------------------------------------------------------------------
__global__ __launch_bounds__(256) void k_wcat(
    const float* __restrict__ W_ih, const float* __restrict__ in2x_w,
    const float* __restrict__ in2x_b, const float* __restrict__ b_ih,
    const float* __restrict__ b_hh, const float* __restrict__ W_hh,
    float* __restrict__ Wx, float* __restrict__ Whh, float* __restrict__ bcomb)
{
    int rp = blockIdx.x;            // 0..2047
    int g = rp & 3, j = rp >> 2;
    int orow = g*HH + j;
    int tid = threadIdx.x;
    __shared__ float wrow[EE];
    __shared__ float red[256];
    wrow[tid] = W_ih[orow*EE + tid];
    __syncthreads();
    float s = 0.f;
    #pragma unroll 8
    for (int i = 0; i < EE; i++) s += wrow[i] * in2x_w[i*1280 + tid];
    Wx[rp*EE + tid] = s;
    Whh[rp*HH + tid]       = W_hh[orow*HH + tid];
    Whh[rp*HH + 256 + tid] = W_hh[orow*HH + 256 + tid];
    red[tid] = wrow[tid] * in2x_b[tid];
    __syncthreads();
    for (int st = 128; st > 0; st >>= 1) {
        if (tid < st) red[tid] += red[tid+st];
        __syncthreads();
    }
    if (tid == 0) bcomb[rp] = red[0] + b_ih[orow] + b_hh[orow];
}

// P2a: u[j] = sum_i Wpg_w[2048+i] * in2x_w[i*1280 + j]
__global__ __launch_bounds__(256) void k_u(
    const float* __restrict__ Wpg, const float* __restrict__ in2x_w,
    float* __restrict__ u)
{
    int j = threadIdx.x;
    float s = 0.f;
    #pragma unroll 8
    for (int i = 0; i < EE; i++) s += Wpg[2048 + i] * in2x_w[i*1280 + j];
    u[j] = s;
}

// P2b: sx[t,b] = inp[t,b,:].u + Wpg_b
__global__ __launch_bounds__(256) void k_sx(
    const float* __restrict__ inp, const float* __restrict__ u,
    const float* __restrict__ Wpg_b, float* __restrict__ sx)
{
    int w = blockIdx.x*8 + (threadIdx.x >> 5);
    int lane = threadIdx.x & 31;
    const float* row = inp + (size_t)w*EE;
    float s = 0.f;
    #pragma unroll
    for (int q = 0; q < 8; q++) s += row[lane + 32*q] * u[lane + 32*q];
    #pragma unroll
    for (int o = 16; o > 0; o >>= 1) s += __shfl_xor_sync(0xffffffffu, s, o);
    if (lane == 0) sx[w] = s + Wpg_b[0];
}

// ---------------------------------------------------------------------------
// Generic 64x64-tile GEMM: C[m,n] = [A0|A1][m,:] . W[n,:] + bias[n]
// K = w0+w1 (multiple of 32). grid (N/64, M/64), 256 threads, 4x4/thread.
// Used for: enc_feat, gates_x, dec_all, out_all.
// ---------------------------------------------------------------------------
__global__ __launch_bounds__(256) void k_tile64(
    const float* __restrict__ A0, int w0,
    const float* __restrict__ A1, int w1,
    const float* __restrict__ W, const float* __restrict__ bias,
    float* __restrict__ C, int N)
{
    __shared__ float As[32][68];
    __shared__ float Ws[32][68];
    int tid = threadIdx.x;
    int m = tid >> 2, kq = tid & 3;
    int tr = tid >> 4, tc = tid & 15;
    int K = w0 + w1;
    float acc[4][4];
    #pragma unroll
    for (int i = 0; i < 4; i++)
        #pragma unroll
        for (int jj = 0; jj < 4; jj++) acc[i][jj] = 0.f;

    size_t mrow = (size_t)blockIdx.y*64 + m;
    const float* Wp = W + ((size_t)blockIdx.x*64 + m)*K;

    for (int k0 = 0; k0 < K; k0 += 32) {
        #pragma unroll
        for (int q = 0; q < 2; q++) {
            int kk0 = q*16 + kq*4;
            int kg = k0 + kk0;
            float4 a4 = (kg < w0) ? *(const float4*)(A0 + mrow*w0 + kg)
                                  : *(const float4*)(A1 + mrow*w1 + kg - w0);
            float4 w4 = *(const float4*)(Wp + kg);
            As[kk0+0][m] = a4.x; As[kk0+1][m] = a4.y; As[kk0+2][m] = a4.z; As[kk0+3][m] = a4.w;
            Ws[kk0+0][m] = w4.x; Ws[kk0+1][m] = w4.y; Ws[kk0+2][m] = w4.z; Ws[kk0+3][m] = w4.w;
        }
        __syncthreads();
        #pragma unroll
        for (int k = 0; k < 32; k++) {
            float4 av = *(const float4*)&As[k][tr*4];
            float4 wv = *(const float4*)&Ws[k][tc*4];
            float a_[4] = {av.x, av.y, av.z, av.w};
            float w_[4] = {wv.x, wv.y, wv.z, wv.w};
            #pragma unroll
            for (int i = 0; i < 4; i++)
                #pragma unroll
                for (int jj = 0; jj < 4; jj++)
                    acc[i][jj] += a_[i]*w_[jj];
        }
        __syncthreads();
    }
    int colb = blockIdx.x*64 + tc*4;
    float4 b4 = *(const float4*)(bias + colb);
    #pragma unroll
    for (int i = 0; i < 4; i++) {
        size_t row = (size_t)blockIdx.y*64 + tr*4 + i;
        float4 o;
        o.x = acc[i][0] + b4.x; o.y = acc[i][1] + b4.y;
        o.z = acc[i][2] + b4.z; o.w = acc[i][3] + b4.w;
        *(float4*)(C + row*N + colb) = o;
    }
}

// ---------------------------------------------------------------------------
// Split-K GEMM for per-step h @ Whh^T: Cpart[ks][m][n], Kchunk=128.
// grid (N/64, K/128), 256 threads, 4x4/thread.
// ---------------------------------------------------------------------------
__global__ __launch_bounds__(256) void k_gemm_sk(
    const float* __restrict__ src, int K,
    const float* __restrict__ W,
    float* __restrict__ Cpart, int N)
{
    __shared__ float As[32][68];
    __shared__ float Ws[32][68];
    int tid = threadIdx.x;
    int m = tid >> 2, kq = tid & 3;
    int tr = tid >> 4, tc = tid & 15;
    int koff = blockIdx.y * 128;
    int nbase = blockIdx.x * 64;
    float acc[4][4];
    #pragma unroll
    for (int i = 0; i < 4; i++)
        #pragma unroll
        for (int jj = 0; jj < 4; jj++) acc[i][jj] = 0.f;

    const float* Wp = W + (size_t)(nbase + m)*K;

    #pragma unroll
    for (int k0 = 0; k0 < 128; k0 += 32) {
        #pragma unroll
        for (int q = 0; q < 2; q++) {
            int kk0 = q*16 + kq*4;
            int kg = koff + k0 + kk0;
            float4 a4 = *(const float4*)(src + m*K + kg);
            float4 w4 = *(const float4*)(Wp + kg);
            As[kk0+0][m] = a4.x; As[kk0+1][m] = a4.y; As[kk0+2][m] = a4.z; As[kk0+3][m] = a4.w;
            Ws[kk0+0][m] = w4.x; Ws[kk0+1][m] = w4.y; Ws[kk0+2][m] = w4.z; Ws[kk0+3][m] = w4.w;
        }
        __syncthreads();
        #pragma unroll
        for (int k = 0; k < 32; k++) {
            float4 av = *(const float4*)&As[k][tr*4];
            float4 wv = *(const float4*)&Ws[k][tc*4];
            float a_[4] = {av.x, av.y, av.z, av.w};
            float w_[4] = {wv.x, wv.y, wv.z, wv.w};
            #pragma unroll
            for (int i = 0; i < 4; i++)
                #pragma unroll
                for (int jj = 0; jj < 4; jj++)
                    acc[i][jj] += a_[i]*w_[jj];
        }
        __syncthreads();
    }
    #pragma unroll
    for (int i = 0; i < 4; i++) {
        int row = tr*4 + i;
        float4 o = make_float4(acc[i][0], acc[i][1], acc[i][2], acc[i][3]);
        *(float4*)(Cpart + ((size_t)blockIdx.y*64 + row)*N + nbase + tc*4) = o;
    }
}

// ---------------------------------------------------------------------------
// S2: gates = gates_x[t] + sum of 4 h-partials -> LSTM elementwise -> h,c
// ---------------------------------------------------------------------------
__global__ __launch_bounds__(256) void k_lstm_ew(
    const float* __restrict__ gpart, const float* __restrict__ gx,
    const float* __restrict__ csrc, float* __restrict__ hdst,
    float* __restrict__ cdst)
{
    int idx = blockIdx.x*256 + threadIdx.x;   // 0..32767
    int b = idx >> 9, j = idx & 511;
    float4 g = ((const float4*)(gx + (size_t)b*H4))[j];
    #pragma unroll
    for (int ks = 0; ks < 4; ks++) {
        float4 p = ((const float4*)(gpart + (size_t)ks*BB*H4 + b*H4))[j];
        g.x += p.x; g.y += p.y; g.z += p.z; g.w += p.w;
    }
    float iv = sigmoidf_(g.x);
    float fv = sigmoidf_(g.y);
    float gv = tanhf(g.z);
    float ov = sigmoidf_(g.w);
    float cn = fv * csrc[b*HH + j] + iv * gv;
    float hn = ov * tanhf(cn);
    cdst[b*HH + j] = cn;
    hdst[b*HH + j] = hn;
}

// ---------------------------------------------------------------------------
// S3: batched scores. grid (25 chunks, 64 b). Each warp owns 2 l-rows held in
// REGISTERS (enc_feat read exactly once from DRAM), loops over all 64 t.
// ---------------------------------------------------------------------------
__global__ __launch_bounds__(256) void k_scores_all(
    const float* __restrict__ ef, const float* __restrict__ dec_all,
    const float* __restrict__ v, float* __restrict__ e_all)
{
    int chunk = blockIdx.x, b = blockIdx.y;
    int warp = threadIdx.x >> 5, lane = threadIdx.x & 31;
    int l0 = chunk*16 + warp*2;

    const float4* efr0 = (const float4*)(ef + ((size_t)b*LL + l0)*HH);
    const float4* efr1 = (const float4*)(ef + ((size_t)b*LL + l0 + 1)*HH);
    const float4* vp   = (const float4*)v;
    float4 f0[4], f1[4], vv[4];
    #pragma unroll
    for (int q = 0; q < 4; q++) {
        f0[q] = efr0[lane + 32*q];
        f1[q] = efr1[lane + 32*q];
        vv[q] = vp  [lane + 32*q];
    }
    for (int t = 0; t < TT; t++) {
        const float4* dp = (const float4*)(dec_all + ((size_t)(t*BB + b))*HH);
        float s0 = 0.f, s1 = 0.f;
        #pragma unroll
        for (int q = 0; q < 4; q++) {
            float4 d = dp[lane + 32*q];
            s0 += vv[q].x*ftanh(f0[q].x + d.x) + vv[q].y*ftanh(f0[q].y + d.y)
                + vv[q].z*ftanh(f0[q].z + d.z) + vv[q].w*ftanh(f0[q].w + d.w);
            s1 += vv[q].x*ftanh(f1[q].x + d.x) + vv[q].y*ftanh(f1[q].y + d.y)
                + vv[q].z*ftanh(f1[q].z + d.z) + vv[q].w*ftanh(f1[q].w + d.w);
        }
        #pragma unroll
        for (int o = 16; o > 0; o >>= 1) {
            s0 += __shfl_xor_sync(0xffffffffu, s0, o);
            s1 += __shfl_xor_sync(0xffffffffu, s1, o);
        }
        if (lane == 0) {
            float* er = e_all + ((size_t)(t*BB + b))*LL + l0;
            er[0] = s0; er[1] = s1;
        }
    }
}

// ---------------------------------------------------------------------------
// S4: batched masked renormalized softmax. One warp per (t,b) row.
// ---------------------------------------------------------------------------
__global__ __launch_bounds__(256) void k_softmax(
    const float* __restrict__ e_all, const float* __restrict__ mask,
    float* __restrict__ attn)
{
    int r = blockIdx.x*8 + (threadIdx.x >> 5);   // (t*64+b)
    int lane = threadIdx.x & 31;
    int b = r & 63;
    const float* er = e_all + (size_t)r*LL;
    const float* mr = mask + b*LL;
    float ev[13];
    float mx = -1e30f;
    #pragma unroll
    for (int i = 0; i < 13; i++) {
        int l = lane + 32*i;
        ev[i] = (l < LL) ? er[l] : -1e30f;
        mx = fmaxf(mx, ev[i]);
    }
    #pragma unroll
    for (int o = 16; o > 0; o >>= 1) mx = fmaxf(mx, __shfl_xor_sync(0xffffffffu, mx, o));
    float sum = 0.f;
    #pragma unroll
    for (int i = 0; i < 13; i++) {
        int l = lane + 32*i;
        float val = (l < LL) ? __expf(ev[i] - mx) * mr[l] : 0.f;
        ev[i] = val;
        sum += val;
    }
    #pragma unroll
    for (int o = 16; o > 0; o >>= 1) sum += __shfl_xor_sync(0xffffffffu, sum, o);
    float inv = 1.f / sum;
    #pragma unroll
    for (int i = 0; i < 13; i++) {
        int l = lane + 32*i;
        if (l < LL) attn[(size_t)r*LL + l] = ev[i] * inv;
    }
}

// ---------------------------------------------------------------------------
// S5: batched ctx as per-b GEMM: C[t,e] = sum_l a[t,b,l] * es[b,l,e]
// grid (16 e-tiles, 64 b), M=64(t), N=64(e), K=400 (BK=16, 25 iters).
// enc_states read exactly once from DRAM.
// ---------------------------------------------------------------------------
__global__ __launch_bounds__(256) void k_ctx(
    const float* __restrict__ attn, const float* __restrict__ es,
    float* __restrict__ ctx_all)
{
    __shared__ float As[16][68];  // [k][t]
    __shared__ float Bs[16][68];  // [k][e]
    int tid = threadIdx.x;
    int b = blockIdx.y, e0 = blockIdx.x*64;
    int tr = tid >> 4, tc = tid & 15;
    float acc[4][4];
    #pragma unroll
    for (int i = 0; i < 4; i++)
        #pragma unroll
        for (int jj = 0; jj < 4; jj++) acc[i][jj] = 0.f;

    int at = tid >> 2, ak4 = (tid & 3)*4;    // A loader: t, k
    int bk = tid >> 4, be4 = (tid & 15)*4;   // B loader: k, e

    for (int it = 0; it < 25; it++) {
        int l0 = it*16;
        float4 a4 = *(const float4*)(attn + ((size_t)at*BB + b)*LL + l0 + ak4);
        As[ak4+0][at] = a4.x; As[ak4+1][at] = a4.y;
        As[ak4+2][at] = a4.z; As[ak4+3][at] = a4.w;
        float4 b4 = *(const float4*)(es + ((size_t)(b*LL + l0 + bk))*H2 + e0 + be4);
        *(float4*)&Bs[bk][be4] = b4;
        __syncthreads();
        #pragma unroll
        for (int k = 0; k < 16; k++) {
            float4 av = *(const float4*)&As[k][tr*4];
            float4 bv = *(const float4*)&Bs[k][tc*4];
            float a_[4] = {av.x, av.y, av.z, av.w};
            float b_[4] = {bv.x, bv.y, bv.z, bv.w};
            #pragma unroll
            for (int i = 0; i < 4; i++)
                #pragma unroll
                for (int jj = 0; jj < 4; jj++)
                    acc[i][jj] += a_[i]*b_[jj];
        }
        __syncthreads();
    }
    #pragma unroll
    for (int i = 0; i < 4; i++) {
        int t = tr*4 + i;
        float4 o = make_float4(acc[i][0], acc[i][1], acc[i][2], acc[i][3]);
        *(float4*)(ctx_all + ((size_t)t*BB + b)*H2 + e0 + tc*4) = o;
    }
}

// ---------------------------------------------------------------------------
// S6: batched p_gen. One warp per (t,b) row.
// ---------------------------------------------------------------------------
__global__ __launch_bounds__(256) void k_pgen(
    const float* __restrict__ ctx_all, const float* __restrict__ h_all,
    const float* __restrict__ c_all, const float* __restrict__ Wpg,
    const float* __restrict__ sx, float* __restrict__ pg)
{
    int r = blockIdx.x*8 + (threadIdx.x >> 5);
    int lane = threadIdx.x & 31;
    const float4* cx = (const float4*)(ctx_all + (size_t)r*H2);
    const float4* hp = (const float4*)(h_all + (size_t)r*HH);
    const float4* cp = (const float4*)(c_all + (size_t)r*HH);
    const float4* w  = (const float4*)Wpg;
    float s = 0.f;
    #pragma unroll
    for (int q = 0; q < 8; q++) {
        float4 f = cx[lane + 32*q], ww = w[lane + 32*q];
        s += f.x*ww.x + f.y*ww.y + f.z*ww.z + f.w*ww.w;
    }
    #pragma unroll
    for (int q = 0; q < 4; q++) {
        float4 f = hp[lane + 32*q], ww = w[256 + lane + 32*q];
        s += f.x*ww.x + f.y*ww.y + f.z*ww.z + f.w*ww.w;
    }
    #pragma unroll
    for (int q = 0; q < 4; q++) {
        float4 f = cp[lane + 32*q], ww = w[384 + lane + 32*q];
        s += f.x*ww.x + f.y*ww.y + f.z*ww.z + f.w*ww.w;
    }
    #pragma unroll
    for (int o = 16; o > 0; o >>= 1) s += __shfl_xor_sync(0xffffffffu, s, o);
    if (lane == 0) pg[r] = 1.f/(1.f + __expf(-(s + sx[r])));
}

__global__ __launch_bounds__(256) void k_copy_hc(
    const float* __restrict__ h, const float* __restrict__ c, float* __restrict__ out)
{
    int i = blockIdx.x*256 + threadIdx.x;   // grid 128 -> 32768
    out[OUT_H + i] = h[i];
    out[OUT_C + i] = c[i];
}

// ---------------------------------------------------------------------------
extern "C" void kernel_launch(void* const* d_in, const int* in_sizes, int n_in,
                              void* d_out, int out_size)
{
    const float* dec_in     = (const float*)d_in[0];
    const float* init_h     = (const float*)d_in[1];
    const float* init_c     = (const float*)d_in[2];
    const float* enc_states = (const float*)d_in[3];
    const float* maskp      = (const float*)d_in[4];
    const float* Ws_w       = (const float*)d_in[5];
    const float* Ws_b       = (const float*)d_in[6];
    const float* in2x_w     = (const float*)d_in[7];
    const float* in2x_b     = (const float*)d_in[8];
    const float* Wpg_w      = (const float*)d_in[9];
    const float* Wpg_b      = (const float*)d_in[10];
    const float* Wout_w     = (const float*)d_in[11];
    const float* Wout_b     = (const float*)d_in[12];
    const float* Wh_w       = (const float*)d_in[13];
    const float* Wh_b       = (const float*)d_in[14];
    const float* vptr       = (const float*)d_in[15];
    const float* W_ih       = (const float*)d_in[16];
    const float* W_hh       = (const float*)d_in[17];
    const float* b_ih       = (const float*)d_in[18];
    const float* b_hh       = (const float*)d_in[19];
    float* out = (float*)d_out;

    float *p_ef, *p_wx, *p_whh, *p_bc, *p_u, *p_sx, *p_gx, *p_gp;
    float *p_ha, *p_ca, *p_da, *p_ea, *p_xa;
    cudaGetSymbolAddress((void**)&p_ef,   g_enc_feat);
    cudaGetSymbolAddress((void**)&p_wx,   g_Wx);
    cudaGetSymbolAddress((void**)&p_whh,  g_Whh);
    cudaGetSymbolAddress((void**)&p_bc,   g_bcomb);
    cudaGetSymbolAddress((void**)&p_u,    g_u);
    cudaGetSymbolAddress((void**)&p_sx,   g_sx);
    cudaGetSymbolAddress((void**)&p_gx,   g_gx_all);
    cudaGetSymbolAddress((void**)&p_gp,   g_gpart);
    cudaGetSymbolAddress((void**)&p_ha,   g_h_all);
    cudaGetSymbolAddress((void**)&p_ca,   g_c_all);
    cudaGetSymbolAddress((void**)&p_da,   g_dec_all);
    cudaGetSymbolAddress((void**)&p_ea,   g_e_all);
    cudaGetSymbolAddress((void**)&p_xa,   g_ctx_all);

    // Precompute (off recurrence path)
    k_wcat<<<H4, 256>>>(W_ih, in2x_w, in2x_b, b_ih, b_hh, W_hh, p_wx, p_whh, p_bc);
    k_u<<<1, 256>>>(Wpg_w, in2x_w, p_u);
    k_sx<<<512, 256>>>(dec_in, p_u, Wpg_b, p_sx);
    // gates_x[t,b] = inp @ Wx^T + bcomb  (M=4096, K=256, N=2048)
    k_tile64<<<dim3(32, 64), 256>>>(dec_in, EE, dec_in, 0, p_wx, p_bc, p_gx, H4);

    // Full LSTM recurrence (only h @ Whh^T per step; attention is off-path)
    for (int t = 0; t < TT; t++) {
        const float* hsrc = (t == 0) ? init_h : p_ha + (size_t)(t - 1)*BH;
        const float* csrc = (t == 0) ? init_c : p_ca + (size_t)(t - 1)*BH;
        k_gemm_sk<<<dim3(32, 4), 256>>>(hsrc, HH, p_whh, p_gp, H4);
        k_lstm_ew<<<128, 256>>>(p_gp, p_gx + (size_t)t*BB*H4, csrc,
                                p_ha + (size_t)t*BH, p_ca + (size_t)t*BH);
    }

    // enc_feat = enc_states @ Wh^T + Wh_b   (M=25600, K=1024, N=512)
    k_tile64<<<dim3(8, 400), 256>>>(enc_states, H2, enc_states, 0,
                                    Wh_w, Wh_b, p_ef, HH);
    // dec_all = [h_all|c_all] @ Ws^T + Ws_b  (M=4096, K=1024, N=512)
    k_tile64<<<dim3(8, 64), 256>>>(p_ha, HH, p_ca, HH, Ws_w, Ws_b, p_da, HH);
    // scores for all (t,b,l)
    k_scores_all<<<dim3(25, 64), 256>>>(p_ef, p_da, vptr, p_ea);
    // masked renormalized softmax -> attn (directly into d_out)
    k_softmax<<<512, 256>>>(p_ea, maskp, out + OUT_ATTN);
    // ctx for all t as per-b GEMMs
    k_ctx<<<dim3(16, 64), 256>>>(out + OUT_ATTN, enc_states, p_xa);
    // p_gen for all (t,b)
    k_pgen<<<512, 256>>>(p_xa, p_ha, p_ca, Wpg_w, p_sx, out + OUT_PG);
    // outputs = [h_all|ctx_all] @ Wout^T + Wout_b  (M=4096, K=1536, N=512)
    k_tile64<<<dim3(8, 64), 256>>>(p_ha, HH, p_xa, H2, Wout_w, Wout_b,
                                   out + OUT_OUTPUTS, HH);
    k_copy_hc<<<128, 256>>>(p_ha + (size_t)(TT-1)*BH, p_ca + (size_t)(TT-1)*BH, out);
}